// round 8
// baseline (speedup 1.0000x reference)
#include <cuda_runtime.h>
#include <cstdint>

// Problem constants
#define NN 50000
#define RR 16
#define DD 200
#define EE 400000
#define NB (RR * NN)
#define S_MAX (EE + 256)
#define NBLK ((NB + 2047) / 2048)

#define TM 128
#define ROOT_TILES ((NN + TM - 1) / TM)    // 391
#define MAX_RTILES 3400
#define GRID_MMA (ROOT_TILES + MAX_RTILES)

#define NP 208                  // padded N
#define KK 200                  // K
#define ASTRIDE 204             // A smem row stride (words)
#define BSTRIDE 40              // B smem row stride (words), 40%32=8 -> v2 conflict-free

// smem byte offsets
#define SM_A   0
#define SM_ASZ (TM * ASTRIDE * 4)            // 104448
#define SM_B0  SM_ASZ
#define SM_BSZ (NP * BSTRIDE * 4)            // 33280
#define SM_B1  (SM_B0 + SM_BSZ)
#define SM_TOTAL (SM_B1 + SM_BSZ + 64)       // ~171KB

// ---------------- device scratch ----------------
__device__ int   g_cnt[NB];
__device__ int   g_slotid[NB];
__device__ int   g_srow[S_MAX];       // slot -> dst node
__device__ float g_sinv[S_MAX];       // slot -> 1/cnt
__device__ int   g_soff[S_MAX + 1];   // slot -> edge offset
__device__ int   g_scursor[S_MAX];
__device__ int   g_esrc[EE];          // edges sorted by slot: src node
__device__ int   g_dcnt[NN];
__device__ int   g_doff[NN + 1];
__device__ int   g_dcur[NN];
__device__ int   g_dslot[S_MAX];      // slots sorted by dst
__device__ unsigned long long g_bsum[NBLK];
__device__ unsigned long long g_bpre[NBLK];
__device__ int   g_roff[RR + 1];
__device__ int   g_S;
__device__ int   g_ntiles;
__device__ int   g_tile_w[MAX_RTILES];
__device__ int   g_tile_m0[MAX_RTILES];
__device__ int   g_tile_rows[MAX_RTILES];
__device__ float g_msg[(long long)S_MAX * DD];   // 320 MB
__device__ float g_h[NN * DD];
__device__ unsigned int g_Wt[17 * NP * KK];      // tf32 W^T, k pair-permuted

// ---------------- helpers ----------------
__device__ __forceinline__ uint32_t s2u(const void* p) {
    uint32_t a;
    asm("{ .reg .u64 t; cvta.to.shared.u64 t, %1; cvt.u32.u64 %0, t; }" : "=r"(a) : "l"(p));
    return a;
}
__device__ __forceinline__ void cpa16(uint32_t dst, const void* src) {
    asm volatile("cp.async.cg.shared.global [%0], [%1], 16;" :: "r"(dst), "l"(src));
}
__device__ __forceinline__ void mma8(float& c0, float& c1, float& c2, float& c3,
                                     uint32_t a0, uint32_t a1, uint32_t a2, uint32_t a3,
                                     uint32_t b0, uint32_t b1) {
    asm volatile(
        "mma.sync.aligned.m16n8k8.row.col.f32.tf32.tf32.f32 "
        "{%0,%1,%2,%3},{%4,%5,%6,%7},{%8,%9},{%0,%1,%2,%3};"
        : "+f"(c0), "+f"(c1), "+f"(c2), "+f"(c3)
        : "r"(a0), "r"(a1), "r"(a2), "r"(a3), "r"(b0), "r"(b1));
}
__device__ __forceinline__ uint32_t rna(uint32_t x) {
    uint32_t t;
    asm("cvt.rna.tf32.f32 %0, %1;" : "=r"(t) : "r"(x));
    return t;
}
__device__ __forceinline__ float rnaf(float x) {
    return __uint_as_float(rna(__float_as_uint(x)));
}

// ---------------- preprocessing ----------------
__global__ void k_zero() {
    int i = blockIdx.x * blockDim.x + threadIdx.x;
    if (i < NB) g_cnt[i] = 0;
    if (i < S_MAX) g_scursor[i] = 0;
    if (i < NN) { g_dcnt[i] = 0; g_dcur[i] = 0; }
}
__global__ void k_hist(const int* __restrict__ etype, const int* __restrict__ dst) {
    int i = blockIdx.x * blockDim.x + threadIdx.x;
    if (i < EE) atomicAdd(&g_cnt[etype[i] * NN + dst[i]], 1);
}
// scan value packing: high 32 = cnt sum, low 32 = flag sum
__global__ void k_scan1() {
    __shared__ unsigned long long wsum[8];
    int b = blockIdx.x, tid = threadIdx.x;
    int i0 = b * 2048 + tid * 8;
    unsigned long long t = 0;
    #pragma unroll
    for (int j = 0; j < 8; j++) {
        int i = i0 + j;
        if (i < NB) {
            int c = g_cnt[i];
            t += (((unsigned long long)c) << 32) | (unsigned)(c > 0);
        }
    }
    int lane = tid & 31, w = tid >> 5;
    #pragma unroll
    for (int o = 16; o > 0; o >>= 1) t += __shfl_down_sync(0xffffffffu, t, o);
    if (lane == 0) wsum[w] = t;
    __syncthreads();
    if (tid == 0) {
        unsigned long long s = 0;
        #pragma unroll
        for (int q = 0; q < 8; q++) s += wsum[q];
        g_bsum[b] = s;
    }
}
__global__ void k_scan2() {
    __shared__ unsigned long long sh[512];
    int tid = threadIdx.x;
    unsigned long long v = (tid < NBLK) ? g_bsum[tid] : 0ull;
    sh[tid] = v;
    __syncthreads();
    for (int off = 1; off < 512; off <<= 1) {
        unsigned long long u = (tid >= off) ? sh[tid - off] : 0ull;
        __syncthreads();
        sh[tid] += u;
        __syncthreads();
    }
    if (tid < NBLK) g_bpre[tid] = sh[tid] - v;
    if (tid == 511) {
        int S = (int)(sh[511] & 0xffffffffull);
        g_S = S;
        g_roff[RR] = S;
    }
}
__global__ void k_scan3() {
    __shared__ unsigned long long wsum[8];
    int b = blockIdx.x, tid = threadIdx.x;
    int i0 = b * 2048 + tid * 8;
    int cj[8];
    unsigned long long loc[8];
    unsigned long long t = 0;
    #pragma unroll
    for (int j = 0; j < 8; j++) {
        int i = i0 + j;
        int c = (i < NB) ? g_cnt[i] : 0;
        cj[j] = c;
        t += (((unsigned long long)c) << 32) | (unsigned)(c > 0);
        loc[j] = t;
    }
    int lane = tid & 31, w = tid >> 5;
    unsigned long long v = t;
    #pragma unroll
    for (int o = 1; o < 32; o <<= 1) {
        unsigned long long u = __shfl_up_sync(0xffffffffu, v, o);
        if (lane >= o) v += u;
    }
    unsigned long long texcl = v - t;
    if (lane == 31) wsum[w] = v;
    __syncthreads();
    if (tid == 0) {
        unsigned long long s = 0;
        #pragma unroll
        for (int q = 0; q < 8; q++) { unsigned long long x = wsum[q]; wsum[q] = s; s += x; }
    }
    __syncthreads();
    unsigned long long base = g_bpre[b] + wsum[w] + texcl;
    #pragma unroll
    for (int j = 0; j < 8; j++) {
        int i = i0 + j;
        if (i < NB) {
            unsigned long long elem = (((unsigned long long)cj[j]) << 32) | (unsigned)(cj[j] > 0);
            unsigned long long pre = base + loc[j] - elem;   // exclusive
            int run = (int)(pre & 0xffffffffull);
            if (i % NN == 0) g_roff[i / NN] = run;
            if (cj[j] > 0) {
                g_slotid[i] = run;
                g_srow[run] = i % NN;
                g_sinv[run] = 1.0f / (float)cj[j];
                g_soff[run] = (int)(pre >> 32);
            }
        }
    }
}
__global__ void k_tiles() {
    __shared__ int tb[RR + 1];
    int tid = threadIdx.x;
    if (tid == 0) {
        int t = 0;
        for (int r = 0; r < RR; r++) {
            tb[r] = t;
            int m = g_roff[r + 1] - g_roff[r];
            t += (m + TM - 1) / TM;
        }
        tb[RR] = t;
        g_ntiles = t;
        g_soff[g_S] = EE;
    }
    __syncthreads();
    int nt = tb[RR];
    for (int i = tid; i < nt; i += blockDim.x) {
        int r = 0;
        while (i >= tb[r + 1]) r++;
        int s0 = g_roff[r] + (i - tb[r]) * TM;
        g_tile_w[i] = r;
        g_tile_m0[i] = s0;
        g_tile_rows[i] = min(TM, g_roff[r + 1] - s0);
    }
}
__global__ void k_sortslot(const int* __restrict__ etype, const int* __restrict__ dst,
                           const int* __restrict__ src) {
    int i = blockIdx.x * blockDim.x + threadIdx.x;
    if (i >= EE) return;
    int slot = g_slotid[etype[i] * NN + dst[i]];
    int pos = g_soff[slot] + atomicAdd(&g_scursor[slot], 1);
    g_esrc[pos] = src[i];
}
__global__ void k_dcnt() {
    int i = blockIdx.x * blockDim.x + threadIdx.x;
    if (i < g_S) atomicAdd(&g_dcnt[g_srow[i]], 1);
}
__global__ void k_dscan() {
    __shared__ int wsum[32];
    int tid = threadIdx.x;             // 1024 threads
    int base = tid * 49;
    int s = 0;
    for (int j = 0; j < 49; j++) {
        int i = base + j;
        if (i < NN) s += g_dcnt[i];
    }
    int lane = tid & 31, w = tid >> 5;
    int v = s;
    #pragma unroll
    for (int o = 1; o < 32; o <<= 1) {
        int u = __shfl_up_sync(0xffffffffu, v, o);
        if (lane >= o) v += u;
    }
    if (lane == 31) wsum[w] = v;
    __syncthreads();
    if (w == 0) {
        int x = wsum[lane];
        int y = x;
        #pragma unroll
        for (int o = 1; o < 32; o <<= 1) {
            int u = __shfl_up_sync(0xffffffffu, y, o);
            if (lane >= o) y += u;
        }
        wsum[lane] = y - x;
    }
    __syncthreads();
    int run = wsum[w] + (v - s);
    for (int j = 0; j < 49; j++) {
        int i = base + j;
        if (i < NN) { g_doff[i] = run; run += g_dcnt[i]; }
    }
    if (tid == 1023) g_doff[NN] = run;
}
__global__ void k_sortdst() {
    int i = blockIdx.x * blockDim.x + threadIdx.x;
    if (i >= g_S) return;
    int d = g_srow[i];
    int pos = g_doff[d] + atomicAdd(&g_dcur[d], 1);
    g_dslot[pos] = i;
}

// g_Wt[w][n][kperm] = tf32_rna(W[w][k][n]); n>=200 -> 0. slot 16 = root.
// k permutation within each 8-group: t -> 2*(t&3) + (t>>2)  (pairs (c4, c4+4) adjacent)
__global__ void k_wt(const float* __restrict__ W, const float* __restrict__ root) {
    int idx = blockIdx.x * blockDim.x + threadIdx.x;
    if (idx >= 17 * NP * KK) return;
    int w = idx / (NP * KK);
    int rem = idx % (NP * KK);
    int n = rem / KK, k = rem % KK;
    float v = 0.0f;
    if (n < 200) v = (w < 16) ? W[w * 40000 + k * 200 + n] : root[k * 200 + n];
    int g = k >> 3, t = k & 7;
    int kp = (g << 3) + ((t & 3) << 1) + (t >> 2);
    g_Wt[w * (NP * KK) + n * KK + kp] = rna(__float_as_uint(v));
}

// out[n] += sum over n's slots of g_msg[slot]; optional relu
__global__ void k_gather(float* __restrict__ out, int do_relu) {
    int idx = blockIdx.x * blockDim.x + threadIdx.x;
    if (idx >= NN * 50) return;
    int n = idx / 50, c = idx % 50;
    float4 v = ((float4*)out)[idx];
    int j0 = g_doff[n], j1 = g_doff[n + 1];
    const float4* m4 = (const float4*)g_msg;
    for (int j = j0; j < j1; j++) {
        float4 u = m4[(long long)g_dslot[j] * 50 + c];
        v.x += u.x; v.y += u.y; v.z += u.z; v.w += u.w;
    }
    if (do_relu) {
        v.x = fmaxf(v.x, 0.f); v.y = fmaxf(v.y, 0.f);
        v.z = fmaxf(v.z, 0.f); v.w = fmaxf(v.w, 0.f);
    }
    ((float4*)out)[idx] = v;
}

// ---------------- fused gather + tf32 mma.sync GEMM ----------------
// blocks [0, ROOT_TILES):  out[m0+row] = X[m0+row]@Wt[16] + bias
// blocks [ROOT_TILES, ..): g_msg[slot] = (sinv * sum_e X[src_e]) @ Wt[r]
__global__ __launch_bounds__(256, 1)
void k_mma(const float* __restrict__ X, float* __restrict__ out,
           const float* __restrict__ bias) {
    extern __shared__ __align__(16) char smem_raw[];
    int t = blockIdx.x;
    bool isroot = (t < ROOT_TILES);
    int wsel, m0, rows;
    if (isroot) {
        wsel = 16; m0 = t * TM; rows = min(TM, NN - m0);
    } else {
        int tt = t - ROOT_TILES;
        if (tt >= g_ntiles) return;
        wsel = g_tile_w[tt]; m0 = g_tile_m0[tt]; rows = g_tile_rows[tt];
    }

    uint32_t sb = s2u(smem_raw);
    float* As = (float*)smem_raw;
    int tid = threadIdx.x;
    int wid = tid >> 5, lane = tid & 31;
    int wm = wid & 3, wn = wid >> 2;
    int r4 = lane >> 2, c4 = lane & 3;

    const unsigned int* Wt = g_Wt + wsel * (NP * KK);

    // prefetch B chunks 0,1 (groups 0,1)
    #pragma unroll
    for (int pc = 0; pc < 2; pc++) {
        uint32_t bo = sb + (pc ? SM_B1 : SM_B0);
        for (int q = tid; q < NP * 10; q += 256) {
            int n = q / 10, h = q % 10;
            cpa16(bo + n * (BSTRIDE * 4) + h * 16, Wt + n * KK + pc * 40 + h * 4);
        }
        asm volatile("cp.async.commit_group;" ::: "memory");
    }

    // ---- A staging: gather-sum + inv-scale + tf32 round ----
    {
        int row = tid >> 1, half = tid & 1;
        const float4* x4 = (const float4*)X;
        float* arow = As + row * ASTRIDE + half * 100;
        if (isroot) {
            int gr = m0 + min(row, rows - 1);
            const float4* xp = x4 + gr * 50 + half * 25;
            #pragma unroll 5
            for (int c = 0; c < 25; c++) {
                float4 u = xp[c];
                u.x = rnaf(u.x); u.y = rnaf(u.y); u.z = rnaf(u.z); u.w = rnaf(u.w);
                *(float4*)(arow + 4 * c) = u;
            }
        } else {
            int slot = m0 + row;
            int e0 = 0, e1 = 0;
            float inv = 0.0f;
            if (row < rows) { e0 = g_soff[slot]; e1 = g_soff[slot + 1]; inv = g_sinv[slot]; }
            for (int c = 0; c < 25; c++) {
                float4 a = make_float4(0.f, 0.f, 0.f, 0.f);
                for (int j = e0; j < e1; j++) {
                    float4 u = x4[g_esrc[j] * 50 + half * 25 + c];
                    a.x += u.x; a.y += u.y; a.z += u.z; a.w += u.w;
                }
                a.x = rnaf(a.x * inv); a.y = rnaf(a.y * inv);
                a.z = rnaf(a.z * inv); a.w = rnaf(a.w * inv);
                *(float4*)(arow + 4 * c) = a;
            }
        }
    }

    float creg[2][13][4];
    #pragma unroll
    for (int mi = 0; mi < 2; mi++)
        #pragma unroll
        for (int ni = 0; ni < 13; ni++)
            #pragma unroll
            for (int q = 0; q < 4; q++) creg[mi][ni][q] = 0.0f;

    int arow0 = wm * 32 + r4;
    int bn0 = wn * 104 + r4;

    for (int cch = 0; cch < 5; cch++) {
        if (cch < 4) asm volatile("cp.async.wait_group 1;" ::: "memory");
        else         asm volatile("cp.async.wait_group 0;" ::: "memory");
        __syncthreads();

        const uint32_t* Bs = (const uint32_t*)(smem_raw + ((cch & 1) ? SM_B1 : SM_B0));
        #pragma unroll
        for (int kk = 0; kk < 5; kk++) {
            uint32_t a[2][4];
            #pragma unroll
            for (int mi = 0; mi < 2; mi++) {
                const float* ap = As + (arow0 + mi * 16) * ASTRIDE + cch * 40 + kk * 8 + c4;
                a[mi][0] = __float_as_uint(ap[0]);
                a[mi][1] = __float_as_uint(ap[8 * ASTRIDE]);
                a[mi][2] = __float_as_uint(ap[4]);
                a[mi][3] = __float_as_uint(ap[8 * ASTRIDE + 4]);
            }
            #pragma unroll
            for (int ni = 0; ni < 13; ni++) {
                uint2 b = *(const uint2*)(Bs + (bn0 + ni * 8) * BSTRIDE + kk * 8 + 2 * c4);
                #pragma unroll
                for (int mi = 0; mi < 2; mi++)
                    mma8(creg[mi][ni][0], creg[mi][ni][1], creg[mi][ni][2], creg[mi][ni][3],
                         a[mi][0], a[mi][1], a[mi][2], a[mi][3], b.x, b.y);
            }
        }
        __syncthreads();
        if (cch + 2 < 5) {
            uint32_t bo = sb + ((cch & 1) ? SM_B1 : SM_B0);
            int kc = (cch + 2) * 40;
            for (int q = tid; q < NP * 10; q += 256) {
                int n = q / 10, h = q % 10;
                cpa16(bo + n * (BSTRIDE * 4) + h * 16, Wt + n * KK + kc + h * 4);
            }
            asm volatile("cp.async.commit_group;" ::: "memory");
        }
    }

    // ---- epilogue: plain stores only (inv already folded into A) ----
    #pragma unroll
    for (int mi = 0; mi < 2; mi++) {
        #pragma unroll
        for (int rr = 0; rr < 2; rr++) {
            int row = wm * 32 + mi * 16 + rr * 8 + r4;
            if (row < rows) {
                float* ob = isroot ? (out + (long long)(m0 + row) * DD)
                                   : (g_msg + (long long)(m0 + row) * DD);
                #pragma unroll
                for (int ni = 0; ni < 13; ni++) {
                    int col = wn * 104 + ni * 8 + 2 * c4;
                    if (col < 200) {
                        float2 o;
                        o.x = creg[mi][ni][2 * rr];
                        o.y = creg[mi][ni][2 * rr + 1];
                        if (isroot) { o.x += bias[col]; o.y += bias[col + 1]; }
                        *(float2*)(ob + col) = o;
                    }
                }
            }
        }
    }
}

// ---------------- launch ----------------
extern "C" void kernel_launch(void* const* d_in, const int* in_sizes, int n_in,
                              void* d_out, int out_size) {
    const int*   edge_index = (const int*)d_in[0];
    const int*   etype      = (const int*)d_in[1];
    const float* emb        = (const float*)d_in[2];
    const float* W1         = (const float*)d_in[3];
    const float* root1      = (const float*)d_in[4];
    const float* b1         = (const float*)d_in[5];
    const float* W2         = (const float*)d_in[6];
    const float* root2      = (const float*)d_in[7];
    const float* b2         = (const float*)d_in[8];
    float* out = (float*)d_out;

    const int* src = edge_index;
    const int* dst = edge_index + EE;

    cudaFuncSetAttribute(k_mma, cudaFuncAttributeMaxDynamicSharedMemorySize, SM_TOTAL);

    int gridNB = (NB + 255) / 256;
    int gridE  = (EE + 255) / 256;
    int gridS  = (S_MAX + 255) / 256;
    int gridWt = (17 * NP * KK + 255) / 256;
    int gridG  = (NN * 50 + 255) / 256;

    // preprocessing (integer atomics only; fp path fully deterministic)
    k_zero<<<gridNB, 256>>>();
    k_hist<<<gridE, 256>>>(etype, dst);
    k_scan1<<<NBLK, 256>>>();
    k_scan2<<<1, 512>>>();
    k_scan3<<<NBLK, 256>>>();
    k_tiles<<<1, 256>>>();
    k_sortslot<<<gridE, 256>>>(etype, dst, src);
    k_dcnt<<<gridS, 256>>>();
    k_dscan<<<1, 1024>>>();
    k_sortdst<<<gridS, 256>>>();

    // layer 1
    k_wt<<<gridWt, 256>>>(W1, root1);
    k_mma<<<GRID_MMA, 256, SM_TOTAL>>>(emb, g_h, b1);
    k_gather<<<gridG, 256>>>(g_h, 1);

    // layer 2
    k_wt<<<gridWt, 256>>>(W2, root2);
    k_mma<<<GRID_MMA, 256, SM_TOTAL>>>(g_h, out, b2);
    k_gather<<<gridG, 256>>>(out, 0);
}

// round 9
// speedup vs baseline: 1.3087x; 1.3087x over previous
#include <cuda_runtime.h>
#include <cstdint>

// Problem constants
#define NN 50000
#define RR 16
#define DD 200
#define EE 400000
#define NB (RR * NN)
#define S_MAX (EE + 256)
#define NBLK ((NB + 2047) / 2048)

#define TM 128
#define ROOT_TILES ((NN + TM - 1) / TM)    // 391
#define MAX_RTILES 3400
#define GRID_MMA (ROOT_TILES + MAX_RTILES)

#define NP 216                  // padded N (3 warps x 72)
#define KK 200                  // K
#define ASTRIDE 204             // A smem row stride (words), conflict-free
#define BSTRIDE 44              // B smem row stride (words), conflict-free (12*r4+c4)

#define NTHREADS 384            // 12 warps: 4(M) x 3(N)

// smem byte offsets
#define SM_A   0
#define SM_ASZ (TM * ASTRIDE * 4)            // 104448
#define SM_B0  SM_ASZ
#define SM_BSZ (NP * BSTRIDE * 4)            // 38016
#define SM_B1  (SM_B0 + SM_BSZ)
#define SM_TOTAL (SM_B1 + SM_BSZ + 64)       // 180544

// ---------------- device scratch ----------------
__device__ int   g_cnt[NB];
__device__ int   g_slotid[NB];
__device__ int   g_srow[S_MAX];       // slot -> dst node
__device__ float g_sinv[S_MAX];       // slot -> 1/cnt
__device__ int   g_soff[S_MAX + 1];   // slot -> edge offset
__device__ int   g_scursor[S_MAX];
__device__ int   g_esrc[EE];          // edges sorted by slot: src node
__device__ int   g_dcnt[NN];
__device__ int   g_doff[NN + 1];
__device__ int   g_dcur[NN];
__device__ int   g_dslot[S_MAX];      // slots sorted by dst
__device__ unsigned long long g_bsum[NBLK];
__device__ unsigned long long g_bpre[NBLK];
__device__ int   g_roff[RR + 1];
__device__ int   g_S;
__device__ int   g_ntiles;
__device__ int   g_tile_w[MAX_RTILES];
__device__ int   g_tile_m0[MAX_RTILES];
__device__ int   g_tile_rows[MAX_RTILES];
__device__ float g_agg[(long long)S_MAX * DD];   // 320 MB (per-slot MEANS)
__device__ float g_msg[(long long)S_MAX * DD];   // 320 MB
__device__ float g_h[NN * DD];
__device__ unsigned int g_Wt[17 * NP * KK];      // tf32 W^T, k pair-permuted

// ---------------- helpers ----------------
__device__ __forceinline__ uint32_t s2u(const void* p) {
    uint32_t a;
    asm("{ .reg .u64 t; cvta.to.shared.u64 t, %1; cvt.u32.u64 %0, t; }" : "=r"(a) : "l"(p));
    return a;
}
__device__ __forceinline__ void cpa16(uint32_t dst, const void* src) {
    asm volatile("cp.async.cg.shared.global [%0], [%1], 16;" :: "r"(dst), "l"(src));
}
__device__ __forceinline__ void mma8(float& c0, float& c1, float& c2, float& c3,
                                     uint32_t a0, uint32_t a1, uint32_t a2, uint32_t a3,
                                     uint32_t b0, uint32_t b1) {
    asm volatile(
        "mma.sync.aligned.m16n8k8.row.col.f32.tf32.tf32.f32 "
        "{%0,%1,%2,%3},{%4,%5,%6,%7},{%8,%9},{%0,%1,%2,%3};"
        : "+f"(c0), "+f"(c1), "+f"(c2), "+f"(c3)
        : "r"(a0), "r"(a1), "r"(a2), "r"(a3), "r"(b0), "r"(b1));
}
__device__ __forceinline__ uint32_t rna(uint32_t x) {
    uint32_t t;
    asm("cvt.rna.tf32.f32 %0, %1;" : "=r"(t) : "r"(x));
    return t;
}

// ---------------- preprocessing ----------------
__global__ void k_zero() {
    int i = blockIdx.x * blockDim.x + threadIdx.x;
    if (i < NB) g_cnt[i] = 0;
    if (i < S_MAX) g_scursor[i] = 0;
    if (i < NN) { g_dcnt[i] = 0; g_dcur[i] = 0; }
}
__global__ void k_hist(const int* __restrict__ etype, const int* __restrict__ dst) {
    int i = blockIdx.x * blockDim.x + threadIdx.x;
    if (i < EE) atomicAdd(&g_cnt[etype[i] * NN + dst[i]], 1);
}
// scan value packing: high 32 = cnt sum, low 32 = flag sum
__global__ void k_scan1() {
    __shared__ unsigned long long wsum[8];
    int b = blockIdx.x, tid = threadIdx.x;
    int i0 = b * 2048 + tid * 8;
    unsigned long long t = 0;
    #pragma unroll
    for (int j = 0; j < 8; j++) {
        int i = i0 + j;
        if (i < NB) {
            int c = g_cnt[i];
            t += (((unsigned long long)c) << 32) | (unsigned)(c > 0);
        }
    }
    int lane = tid & 31, w = tid >> 5;
    #pragma unroll
    for (int o = 16; o > 0; o >>= 1) t += __shfl_down_sync(0xffffffffu, t, o);
    if (lane == 0) wsum[w] = t;
    __syncthreads();
    if (tid == 0) {
        unsigned long long s = 0;
        #pragma unroll
        for (int q = 0; q < 8; q++) s += wsum[q];
        g_bsum[b] = s;
    }
}
__global__ void k_scan2() {
    __shared__ unsigned long long sh[512];
    int tid = threadIdx.x;
    unsigned long long v = (tid < NBLK) ? g_bsum[tid] : 0ull;
    sh[tid] = v;
    __syncthreads();
    for (int off = 1; off < 512; off <<= 1) {
        unsigned long long u = (tid >= off) ? sh[tid - off] : 0ull;
        __syncthreads();
        sh[tid] += u;
        __syncthreads();
    }
    if (tid < NBLK) g_bpre[tid] = sh[tid] - v;
    if (tid == 511) {
        int S = (int)(sh[511] & 0xffffffffull);
        g_S = S;
        g_roff[RR] = S;
    }
}
__global__ void k_scan3() {
    __shared__ unsigned long long wsum[8];
    int b = blockIdx.x, tid = threadIdx.x;
    int i0 = b * 2048 + tid * 8;
    int cj[8];
    unsigned long long loc[8];
    unsigned long long t = 0;
    #pragma unroll
    for (int j = 0; j < 8; j++) {
        int i = i0 + j;
        int c = (i < NB) ? g_cnt[i] : 0;
        cj[j] = c;
        t += (((unsigned long long)c) << 32) | (unsigned)(c > 0);
        loc[j] = t;
    }
    int lane = tid & 31, w = tid >> 5;
    unsigned long long v = t;
    #pragma unroll
    for (int o = 1; o < 32; o <<= 1) {
        unsigned long long u = __shfl_up_sync(0xffffffffu, v, o);
        if (lane >= o) v += u;
    }
    unsigned long long texcl = v - t;
    if (lane == 31) wsum[w] = v;
    __syncthreads();
    if (tid == 0) {
        unsigned long long s = 0;
        #pragma unroll
        for (int q = 0; q < 8; q++) { unsigned long long x = wsum[q]; wsum[q] = s; s += x; }
    }
    __syncthreads();
    unsigned long long base = g_bpre[b] + wsum[w] + texcl;
    #pragma unroll
    for (int j = 0; j < 8; j++) {
        int i = i0 + j;
        if (i < NB) {
            unsigned long long elem = (((unsigned long long)cj[j]) << 32) | (unsigned)(cj[j] > 0);
            unsigned long long pre = base + loc[j] - elem;   // exclusive
            int run = (int)(pre & 0xffffffffull);
            if (i % NN == 0) g_roff[i / NN] = run;
            if (cj[j] > 0) {
                g_slotid[i] = run;
                g_srow[run] = i % NN;
                g_sinv[run] = 1.0f / (float)cj[j];
                g_soff[run] = (int)(pre >> 32);
            }
        }
    }
}
__global__ void k_tiles() {
    __shared__ int tb[RR + 1];
    int tid = threadIdx.x;
    if (tid == 0) {
        int t = 0;
        for (int r = 0; r < RR; r++) {
            tb[r] = t;
            int m = g_roff[r + 1] - g_roff[r];
            t += (m + TM - 1) / TM;
        }
        tb[RR] = t;
        g_ntiles = t;
        g_soff[g_S] = EE;
    }
    __syncthreads();
    int nt = tb[RR];
    for (int i = tid; i < nt; i += blockDim.x) {
        int r = 0;
        while (i >= tb[r + 1]) r++;
        int s0 = g_roff[r] + (i - tb[r]) * TM;
        g_tile_w[i] = r;
        g_tile_m0[i] = s0;
        g_tile_rows[i] = min(TM, g_roff[r + 1] - s0);
    }
}
__global__ void k_sortslot(const int* __restrict__ etype, const int* __restrict__ dst,
                           const int* __restrict__ src) {
    int i = blockIdx.x * blockDim.x + threadIdx.x;
    if (i >= EE) return;
    int slot = g_slotid[etype[i] * NN + dst[i]];
    int pos = g_soff[slot] + atomicAdd(&g_scursor[slot], 1);
    g_esrc[pos] = src[i];
}
__global__ void k_dcnt() {
    int i = blockIdx.x * blockDim.x + threadIdx.x;
    if (i < g_S) atomicAdd(&g_dcnt[g_srow[i]], 1);
}
__global__ void k_dscan() {
    __shared__ int wsum[32];
    int tid = threadIdx.x;             // 1024 threads
    int base = tid * 49;
    int s = 0;
    for (int j = 0; j < 49; j++) {
        int i = base + j;
        if (i < NN) s += g_dcnt[i];
    }
    int lane = tid & 31, w = tid >> 5;
    int v = s;
    #pragma unroll
    for (int o = 1; o < 32; o <<= 1) {
        int u = __shfl_up_sync(0xffffffffu, v, o);
        if (lane >= o) v += u;
    }
    if (lane == 31) wsum[w] = v;
    __syncthreads();
    if (w == 0) {
        int x = wsum[lane];
        int y = x;
        #pragma unroll
        for (int o = 1; o < 32; o <<= 1) {
            int u = __shfl_up_sync(0xffffffffu, y, o);
            if (lane >= o) y += u;
        }
        wsum[lane] = y - x;
    }
    __syncthreads();
    int run = wsum[w] + (v - s);
    for (int j = 0; j < 49; j++) {
        int i = base + j;
        if (i < NN) { g_doff[i] = run; run += g_dcnt[i]; }
    }
    if (tid == 1023) g_doff[NN] = run;
}
__global__ void k_sortdst() {
    int i = blockIdx.x * blockDim.x + threadIdx.x;
    if (i >= g_S) return;
    int d = g_srow[i];
    int pos = g_doff[d] + atomicAdd(&g_dcur[d], 1);
    g_dslot[pos] = i;
}

// g_Wt[w][n][kperm] = tf32_rna(W[w][k][n]); n>=200 -> 0. slot 16 = root.
// Coalesced both sides via 32x32 smem transpose tile.
// k permutation within each 8-group: t -> 2*(t&3) + (t>>2)
__global__ void k_wt(const float* __restrict__ W, const float* __restrict__ root) {
    __shared__ float st[32][33];
    int w  = blockIdx.z;
    int kt = blockIdx.y;   // 0..6 (k tiles)
    int nt = blockIdx.x;   // 0..6 (n tiles)
    int tx = threadIdx.x;  // 0..31
    #pragma unroll
    for (int q = 0; q < 4; q++) {
        int ky = threadIdx.y + 8 * q;          // 0..31
        int k = kt * 32 + ky;
        int n = nt * 32 + tx;
        float v = 0.0f;
        if (k < 200 && n < 200)
            v = (w < 16) ? W[w * 40000 + k * 200 + n] : root[k * 200 + n];
        st[ky][tx] = v;
    }
    __syncthreads();
    #pragma unroll
    for (int q = 0; q < 4; q++) {
        int ny = threadIdx.y + 8 * q;          // 0..31
        int n = nt * 32 + ny;
        int k = kt * 32 + tx;
        if (n < NP && k < 200) {
            int g = k >> 3, t = k & 7;
            int kp = (g << 3) + ((t & 3) << 1) + (t >> 2);
            g_Wt[w * (NP * KK) + n * KK + kp] = rna(__float_as_uint(st[tx][ny]));
        }
    }
}

// segmented MEAN: g_agg[slot] = (1/cnt) * sum over slot's edges of x[src]
__global__ void k_aggseg(const float* __restrict__ x) {
    int idx = blockIdx.x * blockDim.x + threadIdx.x;
    if (idx >= g_S * 50) return;
    int slot = idx / 50, c = idx % 50;
    int e0 = g_soff[slot], e1 = g_soff[slot + 1];
    float inv = g_sinv[slot];
    float4 v = make_float4(0.f, 0.f, 0.f, 0.f);
    const float4* x4 = (const float4*)x;
    for (int j = e0; j < e1; j++) {
        float4 u = x4[g_esrc[j] * 50 + c];
        v.x += u.x; v.y += u.y; v.z += u.z; v.w += u.w;
    }
    v.x *= inv; v.y *= inv; v.z *= inv; v.w *= inv;
    ((float4*)g_agg)[(long long)slot * 50 + c] = v;
}

// out[n] += sum over n's slots of g_msg[slot]; optional relu
__global__ void k_gather(float* __restrict__ out, int do_relu) {
    int idx = blockIdx.x * blockDim.x + threadIdx.x;
    if (idx >= NN * 50) return;
    int n = idx / 50, c = idx % 50;
    float4 v = ((float4*)out)[idx];
    int j0 = g_doff[n], j1 = g_doff[n + 1];
    const float4* m4 = (const float4*)g_msg;
    for (int j = j0; j < j1; j++) {
        float4 u = m4[(long long)g_dslot[j] * 50 + c];
        v.x += u.x; v.y += u.y; v.z += u.z; v.w += u.w;
    }
    if (do_relu) {
        v.x = fmaxf(v.x, 0.f); v.y = fmaxf(v.y, 0.f);
        v.z = fmaxf(v.z, 0.f); v.w = fmaxf(v.w, 0.f);
    }
    ((float4*)out)[idx] = v;
}

// ---------------- tf32 mma.sync GEMM (merged root + relation tiles) ----------------
// blocks [0, ROOT_TILES):  out[m0+row] = X[m0+row]@Wt[16] + bias
// blocks [ROOT_TILES, ..): g_msg[slot] = g_agg[slot] @ Wt[r]   (agg already mean)
// 384 threads = 12 warps; warp grid 4(M) x 3(N); warp tile 32 x 72.
__global__ __launch_bounds__(NTHREADS, 1)
void k_mma(const float* __restrict__ X, float* __restrict__ out,
           const float* __restrict__ bias) {
    extern __shared__ __align__(16) char smem_raw[];
    int t = blockIdx.x;
    bool isroot = (t < ROOT_TILES);
    int wsel, m0, rows;
    if (isroot) {
        wsel = 16; m0 = t * TM; rows = min(TM, NN - m0);
    } else {
        int tt = t - ROOT_TILES;
        if (tt >= g_ntiles) return;
        wsel = g_tile_w[tt]; m0 = g_tile_m0[tt]; rows = g_tile_rows[tt];
    }

    uint32_t sb = s2u(smem_raw);
    const float* As = (const float*)smem_raw;
    int tid = threadIdx.x;
    int wid = tid >> 5, lane = tid & 31;
    int wm = wid & 3, wn = wid >> 2;       // 4(M) x 3(N)
    int r4 = lane >> 2, c4 = lane & 3;

    const unsigned int* Wt = g_Wt + wsel * (NP * KK);
    const float* Ab = isroot ? X : (const float*)g_agg;

    // stage A (group 0)
    for (int q = tid; q < TM * 50; q += NTHREADS) {
        int row = q / 50, s = q % 50;
        int gr = m0 + min(row, rows - 1);
        cpa16(sb + SM_A + row * (ASTRIDE * 4) + s * 16, Ab + (long long)gr * DD + s * 4);
    }
    asm volatile("cp.async.commit_group;" ::: "memory");
    // stage B chunks 0,1 (groups 1,2)
    #pragma unroll
    for (int pc = 0; pc < 2; pc++) {
        uint32_t bo = sb + (pc ? SM_B1 : SM_B0);
        for (int q = tid; q < NP * 10; q += NTHREADS) {
            int n = q / 10, h = q % 10;
            cpa16(bo + n * (BSTRIDE * 4) + h * 16, Wt + n * KK + pc * 40 + h * 4);
        }
        asm volatile("cp.async.commit_group;" ::: "memory");
    }

    float creg[2][9][4];
    #pragma unroll
    for (int mi = 0; mi < 2; mi++)
        #pragma unroll
        for (int ni = 0; ni < 9; ni++)
            #pragma unroll
            for (int q = 0; q < 4; q++) creg[mi][ni][q] = 0.0f;

    int arow0 = wm * 32 + r4;
    int bn0 = wn * 72 + r4;

    for (int cch = 0; cch < 5; cch++) {
        if (cch < 4) asm volatile("cp.async.wait_group 1;" ::: "memory");
        else         asm volatile("cp.async.wait_group 0;" ::: "memory");
        __syncthreads();

        const uint32_t* Bs = (const uint32_t*)(smem_raw + ((cch & 1) ? SM_B1 : SM_B0));
        #pragma unroll
        for (int kk = 0; kk < 5; kk++) {
            uint32_t a[2][4];
            #pragma unroll
            for (int mi = 0; mi < 2; mi++) {
                const float* ap = As + (arow0 + mi * 16) * ASTRIDE + cch * 40 + kk * 8 + c4;
                a[mi][0] = __float_as_uint(ap[0]);
                a[mi][1] = __float_as_uint(ap[8 * ASTRIDE]);
                a[mi][2] = __float_as_uint(ap[4]);
                a[mi][3] = __float_as_uint(ap[8 * ASTRIDE + 4]);
            }
            #pragma unroll
            for (int ni = 0; ni < 9; ni++) {
                // pair-permuted layout: (b0,b1) adjacent words
                const uint32_t* bp = Bs + (bn0 + ni * 8) * BSTRIDE + kk * 8 + 2 * c4;
                uint32_t b0 = bp[0];
                uint32_t b1 = bp[1];
                #pragma unroll
                for (int mi = 0; mi < 2; mi++)
                    mma8(creg[mi][ni][0], creg[mi][ni][1], creg[mi][ni][2], creg[mi][ni][3],
                         a[mi][0], a[mi][1], a[mi][2], a[mi][3], b0, b1);
            }
        }
        __syncthreads();
        if (cch + 2 < 5) {
            uint32_t bo = sb + ((cch & 1) ? SM_B1 : SM_B0);
            int kc = (cch + 2) * 40;
            for (int q = tid; q < NP * 10; q += NTHREADS) {
                int n = q / 10, h = q % 10;
                cpa16(bo + n * (BSTRIDE * 4) + h * 16, Wt + n * KK + kc + h * 4);
            }
            asm volatile("cp.async.commit_group;" ::: "memory");
        }
    }

    // epilogue: plain stores only
    #pragma unroll
    for (int mi = 0; mi < 2; mi++) {
        #pragma unroll
        for (int rr = 0; rr < 2; rr++) {
            int row = wm * 32 + mi * 16 + rr * 8 + r4;
            if (row < rows) {
                float* ob = isroot ? (out + (long long)(m0 + row) * DD)
                                   : (g_msg + (long long)(m0 + row) * DD);
                #pragma unroll
                for (int ni = 0; ni < 9; ni++) {
                    int col = wn * 72 + ni * 8 + 2 * c4;
                    if (col < 200) {
                        float2 o;
                        o.x = creg[mi][ni][2 * rr];
                        o.y = creg[mi][ni][2 * rr + 1];
                        if (isroot) { o.x += bias[col]; o.y += bias[col + 1]; }
                        *(float2*)(ob + col) = o;
                    }
                }
            }
        }
    }
}

// ---------------- launch ----------------
extern "C" void kernel_launch(void* const* d_in, const int* in_sizes, int n_in,
                              void* d_out, int out_size) {
    const int*   edge_index = (const int*)d_in[0];
    const int*   etype      = (const int*)d_in[1];
    const float* emb        = (const float*)d_in[2];
    const float* W1         = (const float*)d_in[3];
    const float* root1      = (const float*)d_in[4];
    const float* b1         = (const float*)d_in[5];
    const float* W2         = (const float*)d_in[6];
    const float* root2      = (const float*)d_in[7];
    const float* b2         = (const float*)d_in[8];
    float* out = (float*)d_out;

    const int* src = edge_index;
    const int* dst = edge_index + EE;

    cudaFuncSetAttribute(k_mma, cudaFuncAttributeMaxDynamicSharedMemorySize, SM_TOTAL);

    int gridNB = (NB + 255) / 256;
    int gridE  = (EE + 255) / 256;
    int gridS  = (S_MAX + 255) / 256;
    int gridSeg = (S_MAX * 50 + 255) / 256;
    int gridG  = (NN * 50 + 255) / 256;
    dim3 gridWt(7, 7, 17), blkWt(32, 8);

    // preprocessing (integer atomics only; fp path fully deterministic)
    k_zero<<<gridNB, 256>>>();
    k_hist<<<gridE, 256>>>(etype, dst);
    k_scan1<<<NBLK, 256>>>();
    k_scan2<<<1, 512>>>();
    k_scan3<<<NBLK, 256>>>();
    k_tiles<<<1, 256>>>();
    k_sortslot<<<gridE, 256>>>(etype, dst, src);
    k_dcnt<<<gridS, 256>>>();
    k_dscan<<<1, 1024>>>();
    k_sortdst<<<gridS, 256>>>();

    // layer 1
    k_wt<<<gridWt, blkWt>>>(W1, root1);
    k_aggseg<<<gridSeg, 256>>>(emb);
    k_mma<<<GRID_MMA, NTHREADS, SM_TOTAL>>>(emb, g_h, b1);
    k_gather<<<gridG, 256>>>(g_h, 1);

    // layer 2
    k_wt<<<gridWt, blkWt>>>(W2, root2);
    k_aggseg<<<gridSeg, 256>>>(g_h);
    k_mma<<<GRID_MMA, NTHREADS, SM_TOTAL>>>(g_h, out, b2);
    k_gather<<<gridG, 256>>>(out, 0);
}